// round 14
// baseline (speedup 1.0000x reference)
#include <cuda_runtime.h>
#include <stdint.h>

#define HIDDEN 128
#define NRAD   6

__global__ void zero_out_kernel(float4* __restrict__ out, int n4) {
    int idx = blockIdx.x * blockDim.x + threadIdx.x;
    int stride = gridDim.x * blockDim.x;
    for (int k = idx; k < n4; k += stride)
        out[k] = make_float4(0.f, 0.f, 0.f, 0.f);
}

// Batch = 4 pairs = 8 edges. Double-buffered x rows in registers:
// 8 LDG.128 (4KB) in flight per warp. 16 warps/SM -> 64KB/SM in flight (~3x knee).
// rbf/idx lines prefetched to L1 one batch ahead. W register-resident.
__global__ void __launch_bounds__(128, 4)
fused_rbf_scatter_kernel(const float* __restrict__ x,
                         const float* __restrict__ rbf,
                         const float* __restrict__ W,   // [HIDDEN, NRAD] row-major
                         const int* __restrict__ idx,   // int32 edge indices
                         float* __restrict__ out,
                         int E)
{
    const int lane  = threadIdx.x & 31;
    const int wid   = (blockIdx.x * blockDim.x + threadIdx.x) >> 5;
    const int nwarp = (gridDim.x * blockDim.x) >> 5;

    // This lane's 4 rows of W (24 floats) in registers, loaded once.
    const int hbase = lane * 4;
    float w00,w01,w02,w03,w04,w05;
    float w10,w11,w12,w13,w14,w15;
    float w20,w21,w22,w23,w24,w25;
    float w30,w31,w32,w33,w34,w35;
    {
        const float* p = W + hbase * NRAD;
        w00=p[0];  w01=p[1];  w02=p[2];  w03=p[3];  w04=p[4];  w05=p[5];
        w10=p[6];  w11=p[7];  w12=p[8];  w13=p[9];  w14=p[10]; w15=p[11];
        w20=p[12]; w21=p[13]; w22=p[14]; w23=p[15]; w24=p[16]; w25=p[17];
        w30=p[18]; w31=p[19]; w32=p[20]; w33=p[21]; w34=p[22]; w35=p[23];
    }

    const float4* __restrict__ x4   = reinterpret_cast<const float4*>(x);
    const float4* __restrict__ rbf4 = reinterpret_cast<const float4*>(rbf);
    const int2*   __restrict__ idx2 = reinterpret_cast<const int2*>(idx);

    const int pairsFull = E >> 1;
    const int chunk = (pairsFull + nwarp - 1) / nwarp;
    int p    = wid * chunk;
    int pend = p + chunk;
    if (pend > pairsFull) pend = pairsFull;

    // ================= batched main loop (4 pairs / iter) =================
    if (pend - p >= 4) {
        float4 xa[8], xb[8];
#pragma unroll
        for (int j = 0; j < 8; ++j)
            xa[j] = __ldcs(x4 + (size_t)(2 * p + j) * 32 + lane);

        while (pend - p >= 4) {
            const bool more = (pend - p >= 8);

            // ---- prefetch next batch: x into regs, rbf/idx lines into L1 ----
            if (more) {
#pragma unroll
                for (int j = 0; j < 8; ++j)
                    xb[j] = __ldcs(x4 + (size_t)(2 * p + 8 + j) * 32 + lane);
                // next batch's rbf spans 192B (2 lines); idx 32B (1 line)
                if (lane < 2)
                    asm volatile("prefetch.global.L1 [%0];"
                                 :: "l"((const char*)(rbf4 + 3 * (size_t)(p + 4)) + lane * 128));
                else if (lane == 2)
                    asm volatile("prefetch.global.L1 [%0];"
                                 :: "l"((const char*)(idx2 + (p + 4))));
            }

            // ---- process current batch's 4 pairs ----
#pragma unroll
            for (int q = 0; q < 4; ++q) {
                const int pp = p + q;
                int2   nodes = __ldcs(idx2 + pp);
                float4 f0 = __ldcs(rbf4 + 3 * (size_t)pp);
                float4 f1 = __ldcs(rbf4 + 3 * (size_t)pp + 1);
                float4 f2 = __ldcs(rbf4 + 3 * (size_t)pp + 2);

                // edge0: rbf = {f0.x,f0.y,f0.z,f0.w,f1.x,f1.y}
                float c0 = fmaf(f0.x, w00, fmaf(f0.y, w01, fmaf(f0.z, w02,
                           fmaf(f0.w, w03, fmaf(f1.x, w04, f1.y * w05)))));
                float c1 = fmaf(f0.x, w10, fmaf(f0.y, w11, fmaf(f0.z, w12,
                           fmaf(f0.w, w13, fmaf(f1.x, w14, f1.y * w15)))));
                float c2 = fmaf(f0.x, w20, fmaf(f0.y, w21, fmaf(f0.z, w22,
                           fmaf(f0.w, w23, fmaf(f1.x, w24, f1.y * w25)))));
                float c3 = fmaf(f0.x, w30, fmaf(f0.y, w31, fmaf(f0.z, w32,
                           fmaf(f0.w, w33, fmaf(f1.x, w34, f1.y * w35)))));

                // edge1: rbf = {f1.z,f1.w,f2.x,f2.y,f2.z,f2.w}
                float d0 = fmaf(f1.z, w00, fmaf(f1.w, w01, fmaf(f2.x, w02,
                           fmaf(f2.y, w03, fmaf(f2.z, w04, f2.w * w05)))));
                float d1 = fmaf(f1.z, w10, fmaf(f1.w, w11, fmaf(f2.x, w12,
                           fmaf(f2.y, w13, fmaf(f2.z, w14, f2.w * w15)))));
                float d2 = fmaf(f1.z, w20, fmaf(f1.w, w21, fmaf(f2.x, w22,
                           fmaf(f2.y, w23, fmaf(f2.z, w24, f2.w * w25)))));
                float d3 = fmaf(f1.z, w30, fmaf(f1.w, w31, fmaf(f2.x, w32,
                           fmaf(f2.y, w33, fmaf(f2.z, w34, f2.w * w35)))));

                const float4 xv0 = xa[2 * q];
                const float4 xv1 = xa[2 * q + 1];

                float* dst0 = out + (size_t)nodes.x * HIDDEN + hbase;
                asm volatile("red.global.add.v4.f32 [%0], {%1, %2, %3, %4};"
                             :: "l"(dst0), "f"(c0 * xv0.x), "f"(c1 * xv0.y),
                                "f"(c2 * xv0.z), "f"(c3 * xv0.w) : "memory");
                float* dst1 = out + (size_t)nodes.y * HIDDEN + hbase;
                asm volatile("red.global.add.v4.f32 [%0], {%1, %2, %3, %4};"
                             :: "l"(dst1), "f"(d0 * xv1.x), "f"(d1 * xv1.y),
                                "f"(d2 * xv1.z), "f"(d3 * xv1.w) : "memory");
            }

            if (more) {
#pragma unroll
                for (int j = 0; j < 8; ++j) xa[j] = xb[j];
            }
            p += 4;
        }
    }

    // ================= leftover pairs (<4) =================
    for (; p < pend; ++p) {
        int2   nodes = __ldcs(idx2 + p);
        float4 f0 = __ldcs(rbf4 + 3 * (size_t)p);
        float4 f1 = __ldcs(rbf4 + 3 * (size_t)p + 1);
        float4 f2 = __ldcs(rbf4 + 3 * (size_t)p + 2);
        float4 xv0 = __ldcs(x4 + (size_t)(2 * p)     * 32 + lane);
        float4 xv1 = __ldcs(x4 + (size_t)(2 * p + 1) * 32 + lane);

        float c0 = fmaf(f0.x, w00, fmaf(f0.y, w01, fmaf(f0.z, w02,
                   fmaf(f0.w, w03, fmaf(f1.x, w04, f1.y * w05)))));
        float c1 = fmaf(f0.x, w10, fmaf(f0.y, w11, fmaf(f0.z, w12,
                   fmaf(f0.w, w13, fmaf(f1.x, w14, f1.y * w15)))));
        float c2 = fmaf(f0.x, w20, fmaf(f0.y, w21, fmaf(f0.z, w22,
                   fmaf(f0.w, w23, fmaf(f1.x, w24, f1.y * w25)))));
        float c3 = fmaf(f0.x, w30, fmaf(f0.y, w31, fmaf(f0.z, w32,
                   fmaf(f0.w, w33, fmaf(f1.x, w34, f1.y * w35)))));
        float d0 = fmaf(f1.z, w00, fmaf(f1.w, w01, fmaf(f2.x, w02,
                   fmaf(f2.y, w03, fmaf(f2.z, w04, f2.w * w05)))));
        float d1 = fmaf(f1.z, w10, fmaf(f1.w, w11, fmaf(f2.x, w12,
                   fmaf(f2.y, w13, fmaf(f2.z, w14, f2.w * w15)))));
        float d2 = fmaf(f1.z, w20, fmaf(f1.w, w21, fmaf(f2.x, w22,
                   fmaf(f2.y, w23, fmaf(f2.z, w24, f2.w * w25)))));
        float d3 = fmaf(f1.z, w30, fmaf(f1.w, w31, fmaf(f2.x, w32,
                   fmaf(f2.y, w33, fmaf(f2.z, w34, f2.w * w35)))));

        float* dst0 = out + (size_t)nodes.x * HIDDEN + hbase;
        asm volatile("red.global.add.v4.f32 [%0], {%1, %2, %3, %4};"
                     :: "l"(dst0), "f"(c0 * xv0.x), "f"(c1 * xv0.y),
                        "f"(c2 * xv0.z), "f"(c3 * xv0.w) : "memory");
        float* dst1 = out + (size_t)nodes.y * HIDDEN + hbase;
        asm volatile("red.global.add.v4.f32 [%0], {%1, %2, %3, %4};"
                     :: "l"(dst1), "f"(d0 * xv1.x), "f"(d1 * xv1.y),
                        "f"(d2 * xv1.z), "f"(d3 * xv1.w) : "memory");
    }

    // ================= odd tail edge =================
    if ((E & 1) && wid == 0) {
        const int e = E - 1;
        int node = idx[e];
        const float2* r2 = reinterpret_cast<const float2*>(rbf) + 3 * (size_t)e;
        float2 g0 = r2[0], g1 = r2[1], g2 = r2[2];
        float4 xv = x4[(size_t)e * 32 + lane];

        float c0 = fmaf(g0.x, w00, fmaf(g0.y, w01, fmaf(g1.x, w02,
                   fmaf(g1.y, w03, fmaf(g2.x, w04, g2.y * w05)))));
        float c1 = fmaf(g0.x, w10, fmaf(g0.y, w11, fmaf(g1.x, w12,
                   fmaf(g1.y, w13, fmaf(g2.x, w14, g2.y * w15)))));
        float c2 = fmaf(g0.x, w20, fmaf(g0.y, w21, fmaf(g1.x, w22,
                   fmaf(g1.y, w23, fmaf(g2.x, w24, g2.y * w25)))));
        float c3 = fmaf(g0.x, w30, fmaf(g0.y, w31, fmaf(g1.x, w32,
                   fmaf(g1.y, w33, fmaf(g2.x, w34, g2.y * w35)))));

        float* dst = out + (size_t)node * HIDDEN + hbase;
        asm volatile("red.global.add.v4.f32 [%0], {%1, %2, %3, %4};"
                     :: "l"(dst), "f"(c0 * xv.x), "f"(c1 * xv.y),
                        "f"(c2 * xv.z), "f"(c3 * xv.w) : "memory");
    }
}

extern "C" void kernel_launch(void* const* d_in, const int* in_sizes, int n_in,
                              void* d_out, int out_size)
{
    const float* x   = (const float*)d_in[0];   // [E, 128]
    const float* rbf = (const float*)d_in[1];   // [E, 6]
    const float* W   = (const float*)d_in[2];   // [128, 6]
    const int*   idx = (const int*)d_in[3];     // [E] int32
    float*       out = (float*)d_out;           // [num_nodes, 128]

    const int E = in_sizes[0] / HIDDEN;

    // Zero output (poisoned to 0xAA by harness)
    {
        int n4 = out_size / 4;
        int threads = 256;
        int blocks = (n4 + threads - 1) / threads;
        if (blocks > 8192) blocks = 8192;
        zero_out_kernel<<<blocks, threads>>>((float4*)out, n4);
    }

    // Fused compute + scatter-add: 4 CTAs/SM * 148 SMs, 4 warps each.
    {
        int threads = 128;
        int blocks  = 148 * 4;              // 592 blocks -> 2368 warps
        int pairs = E >> 1;
        int max_blocks = (pairs + 3) / 4;
        if (max_blocks < 1) max_blocks = 1;
        if (blocks > max_blocks) blocks = max_blocks;
        fused_rbf_scatter_kernel<<<blocks, threads>>>(x, rbf, W, idx, out, E);
    }
}